// round 1
// baseline (speedup 1.0000x reference)
#include <cuda_runtime.h>

#define N_ROWS 32768
#define N_CODES 8192
#define DIM 64
#define HW 4096
#define ZB 262144
#define NELEM 2097152
#define TR 128
#define TC 128
#define NCHUNK (N_CODES / TC)
#define SMEM_BYTES ((DIM * 2 * TR + DIM * TC) * 4)

__device__ int    g_idx[N_ROWS];
__device__ float  g_A[N_ROWS];
__device__ float  g_B[N_CODES];
__device__ float  g_embT[DIM * N_CODES];
__device__ double g_partial[2048];

__device__ __forceinline__ unsigned long long pack2(float lo, float hi) {
    unsigned long long r;
    asm("mov.b64 %0, {%1, %2};" : "=l"(r) : "f"(lo), "f"(hi));
    return r;
}
__device__ __forceinline__ void unpack2(unsigned long long v, float& lo, float& hi) {
    asm("mov.b64 {%0, %1}, %2;" : "=f"(lo), "=f"(hi) : "l"(v));
}
__device__ __forceinline__ void fma2(unsigned long long& d, unsigned long long a, unsigned long long b) {
    asm("fma.rn.f32x2 %0, %1, %2, %0;" : "+l"(d) : "l"(a), "l"(b));
}

// ---------------------------------------------------------------------------
// Prologue: embT transpose, A = ||z||^2 per row, B = ||e||^2 per code, zero scratch
// ---------------------------------------------------------------------------
__global__ void vq_prep(const float* __restrict__ z, const float* __restrict__ emb) {
    int t = blockIdx.x * blockDim.x + threadIdx.x;
    if (t < DIM * N_CODES) {
        int j = t >> 6;
        int c = t & 63;
        g_embT[c * N_CODES + j] = emb[t];
    }
    if (t < N_ROWS) {
        int b = t >> 12, hw = t & 4095;
        const float* zp = z + b * ZB + hw;
        float s = 0.f;
#pragma unroll
        for (int c = 0; c < DIM; c++) {
            float v = zp[c * HW];
            s = __fmaf_rn(v, v, s);
        }
        g_A[t] = s;
    }
    if (t < N_CODES) {
        const float4* ep = (const float4*)(emb + t * DIM);
        float s = 0.f;
#pragma unroll
        for (int i = 0; i < 16; i++) {
            float4 v = ep[i];
            s = __fmaf_rn(v.x, v.x, s);
            s = __fmaf_rn(v.y, v.y, s);
            s = __fmaf_rn(v.z, v.z, s);
            s = __fmaf_rn(v.w, v.w, s);
        }
        g_B[t] = s;
    }
}

// ---------------------------------------------------------------------------
// Main: fused distance GEMM + argmin.
// Block: 128 rows x all 8192 codes (looped in 128-code chunks).
// 256 threads (16x16), each thread 8 rows x 8 codes, f32x2-packed along codes.
// z tile stored duplicated in smem so the outer product needs no per-k packing.
// ---------------------------------------------------------------------------
__global__ __launch_bounds__(256, 2) void vq_argmin(const float* __restrict__ z,
                                                    float* __restrict__ outF) {
    extern __shared__ float sm[];
    float* zshd = sm;                   // [64][256]  row-duplicated z tile (64KB)
    float* esh  = sm + DIM * 2 * TR;    // [64][128]  e chunk, k-major (32KB)

    int tid = threadIdx.x;
    int tx = tid & 15, ty = tid >> 4;
    int row0 = blockIdx.x * TR;
    int bb = row0 >> 12, hw0 = row0 & 4095;
    const float* zb = z + bb * ZB + hw0;

    // Load z tile [64 k][128 r], duplicating each row value: zshd[k][2r]=zshd[k][2r+1]=z
#pragma unroll
    for (int i = 0; i < 8; i++) {
        int q = tid + i * 256;          // 2048 float4s
        int c = q >> 5;
        int r4 = (q & 31) << 2;
        float4 v = *(const float4*)(zb + c * HW + r4);
        float2* dst = (float2*)(zshd + c * (2 * TR) + r4 * 2);
        dst[0] = make_float2(v.x, v.x);
        dst[1] = make_float2(v.y, v.y);
        dst[2] = make_float2(v.z, v.z);
        dst[3] = make_float2(v.w, v.w);
    }

    float Ar[8];
    {
        const float4* ap = (const float4*)(g_A + row0 + ty * 8);
        float4 a0 = ap[0], a1 = ap[1];
        Ar[0] = a0.x; Ar[1] = a0.y; Ar[2] = a0.z; Ar[3] = a0.w;
        Ar[4] = a1.x; Ar[5] = a1.y; Ar[6] = a1.z; Ar[7] = a1.w;
    }
    unsigned long long Au[8];
#pragma unroll
    for (int u = 0; u < 8; u++) Au[u] = pack2(Ar[u], Ar[u]);

    const unsigned long long neg1 = pack2(-1.0f, -1.0f);
    const unsigned long long two2 = pack2(2.0f, 2.0f);

    float best[8];
    int bestj[8];
#pragma unroll
    for (int u = 0; u < 8; u++) { best[u] = __int_as_float(0x7f800000); bestj[u] = 0; }

    for (int ch = 0; ch < NCHUNK; ch++) {
        __syncthreads();
        // Load e chunk (k-major from pre-transposed embT): coalesced, conflict-free
#pragma unroll
        for (int i = 0; i < 8; i++) {
            int q = tid + i * 256;      // 2048 float4s
            int c = q >> 5;
            int j4 = (q & 31) << 2;
            *(float4*)(esh + c * TC + j4) =
                *(const float4*)(g_embT + c * N_CODES + ch * TC + j4);
        }
        __syncthreads();

        // B fragment for this chunk
        float Bj[8];
        {
            const float4* bp = (const float4*)(g_B + ch * TC + tx * 8);
            float4 b0 = bp[0], b1 = bp[1];
            Bj[0] = b0.x; Bj[1] = b0.y; Bj[2] = b0.z; Bj[3] = b0.w;
            Bj[4] = b1.x; Bj[5] = b1.y; Bj[6] = b1.z; Bj[7] = b1.w;
        }

        unsigned long long acc[8][4];
#pragma unroll
        for (int u = 0; u < 8; u++)
#pragma unroll
            for (int p = 0; p < 4; p++) acc[u][p] = 0ull;

#pragma unroll 8
        for (int k = 0; k < DIM; k++) {
            const ulonglong2* zp = (const ulonglong2*)(zshd + k * (2 * TR) + ty * 16);
            ulonglong2 za = zp[0], zc = zp[1], zd = zp[2], ze = zp[3];
            const ulonglong2* ep = (const ulonglong2*)(esh + k * TC + tx * 8);
            ulonglong2 ea = ep[0], eb = ep[1];

            fma2(acc[0][0], za.x, ea.x); fma2(acc[0][1], za.x, ea.y);
            fma2(acc[0][2], za.x, eb.x); fma2(acc[0][3], za.x, eb.y);
            fma2(acc[1][0], za.y, ea.x); fma2(acc[1][1], za.y, ea.y);
            fma2(acc[1][2], za.y, eb.x); fma2(acc[1][3], za.y, eb.y);
            fma2(acc[2][0], zc.x, ea.x); fma2(acc[2][1], zc.x, ea.y);
            fma2(acc[2][2], zc.x, eb.x); fma2(acc[2][3], zc.x, eb.y);
            fma2(acc[3][0], zc.y, ea.x); fma2(acc[3][1], zc.y, ea.y);
            fma2(acc[3][2], zc.y, eb.x); fma2(acc[3][3], zc.y, eb.y);
            fma2(acc[4][0], zd.x, ea.x); fma2(acc[4][1], zd.x, ea.y);
            fma2(acc[4][2], zd.x, eb.x); fma2(acc[4][3], zd.x, eb.y);
            fma2(acc[5][0], zd.y, ea.x); fma2(acc[5][1], zd.y, ea.y);
            fma2(acc[5][2], zd.y, eb.x); fma2(acc[5][3], zd.y, eb.y);
            fma2(acc[6][0], ze.x, ea.x); fma2(acc[6][1], ze.x, ea.y);
            fma2(acc[6][2], ze.x, eb.x); fma2(acc[6][3], ze.x, eb.y);
            fma2(acc[7][0], ze.y, ea.x); fma2(acc[7][1], ze.y, ea.y);
            fma2(acc[7][2], ze.y, eb.x); fma2(acc[7][3], ze.y, eb.y);
        }

        // Epilogue: d = fl(fl(A + B) - fl(2*dot)), running argmin (strict < keeps first j)
        unsigned long long Bp[4];
#pragma unroll
        for (int p = 0; p < 4; p++) Bp[p] = pack2(Bj[2 * p], Bj[2 * p + 1]);

        int jb = ch * TC + tx * 8;
#pragma unroll
        for (int u = 0; u < 8; u++) {
#pragma unroll
            for (int p = 0; p < 4; p++) {
                unsigned long long tt, mm, dd;
                asm("add.rn.f32x2 %0, %1, %2;" : "=l"(tt) : "l"(Au[u]), "l"(Bp[p]));
                asm("mul.rn.f32x2 %0, %1, %2;" : "=l"(mm) : "l"(acc[u][p]), "l"(two2));
                asm("fma.rn.f32x2 %0, %1, %2, %3;" : "=l"(dd) : "l"(mm), "l"(neg1), "l"(tt));
                float d0, d1;
                unpack2(dd, d0, d1);
                if (d0 < best[u]) { best[u] = d0; bestj[u] = jb + 2 * p; }
                if (d1 < best[u]) { best[u] = d1; bestj[u] = jb + 2 * p + 1; }
            }
        }
    }

    // Cross-thread reduction per row (16 candidates), tie -> smaller j
    __syncthreads();
    float* cd = esh;                    // [16][128]
    int*   cj = (int*)(esh + 16 * 128); // [16][128]
#pragma unroll
    for (int u = 0; u < 8; u++) {
        int r = ty * 8 + u;
        cd[tx * 128 + r] = best[u];
        cj[tx * 128 + r] = bestj[u];
    }
    __syncthreads();
    if (tid < 128) {
        int r = tid;
        float bd = cd[r];
        int bj = cj[r];
#pragma unroll
        for (int t = 1; t < 16; t++) {
            float d = cd[t * 128 + r];
            int j = cj[t * 128 + r];
            if (d < bd || (d == bd && j < bj)) { bd = d; bj = j; }
        }
        int row = row0 + r;
        g_idx[row] = bj;
        outF[1 + NELEM + row] = (float)bj;
    }
}

// ---------------------------------------------------------------------------
// Output: z_q straight-through (replicates fl(z + fl(e - z))) + loss partials
// ---------------------------------------------------------------------------
__global__ void vq_out(const float* __restrict__ z, const float* __restrict__ emb,
                       float* __restrict__ outF) {
    int t = blockIdx.x * 1024 + threadIdx.x;
    int c = (t >> 12) & 63;
    int n = ((t >> 18) << 12) | (t & 4095);
    int idx = g_idx[n];
    float zv = z[t];
    float e = emb[idx * 64 + c];
    float d1 = __fsub_rn(e, zv);
    outF[1 + t] = __fadd_rn(zv, d1);
    double s = (double)__fmul_rn(d1, d1);
#pragma unroll
    for (int o = 16; o; o >>= 1) s += __shfl_down_sync(0xffffffffu, s, o);
    __shared__ double ws[32];
    int lane = threadIdx.x & 31, w = threadIdx.x >> 5;
    if (lane == 0) ws[w] = s;
    __syncthreads();
    if (w == 0) {
        double v = ws[lane];
#pragma unroll
        for (int o = 16; o; o >>= 1) v += __shfl_down_sync(0xffffffffu, v, o);
        if (lane == 0) g_partial[blockIdx.x] = v;
    }
}

// Deterministic final reduce + loss = 1.25 * mse (matches fl(m + fl(0.25*m)))
__global__ void vq_loss(float* __restrict__ outF) {
    __shared__ double sh[256];
    double s = 0.0;
    for (int i = threadIdx.x; i < 2048; i += 256) s += g_partial[i];
    sh[threadIdx.x] = s;
    __syncthreads();
    for (int st = 128; st; st >>= 1) {
        if (threadIdx.x < st) sh[threadIdx.x] += sh[threadIdx.x + st];
        __syncthreads();
    }
    if (threadIdx.x == 0) {
        float m = (float)(sh[0] / (double)NELEM);
        outF[0] = __fadd_rn(m, __fmul_rn(0.25f, m));
    }
}

extern "C" void kernel_launch(void* const* d_in, const int* in_sizes, int n_in,
                              void* d_out, int out_size) {
    const float* z = (const float*)d_in[0];
    const float* emb = (const float*)d_in[1];
    float* out = (float*)d_out;

    cudaFuncSetAttribute(vq_argmin, cudaFuncAttributeMaxDynamicSharedMemorySize, SMEM_BYTES);

    vq_prep<<<2048, 256>>>(z, emb);
    vq_argmin<<<N_ROWS / TR, 256, SMEM_BYTES>>>(z, out);
    vq_out<<<2048, 1024>>>(z, emb, out);
    vq_loss<<<1, 256>>>(out);
}

// round 2
// speedup vs baseline: 1.0805x; 1.0805x over previous
#include <cuda_runtime.h>

#define N_ROWS 32768
#define N_CODES 8192
#define DIM 64
#define HW 4096
#define ZB 262144
#define NELEM 2097152
#define TR 128
#define TC 128
#define NCHUNK (N_CODES / TC)
// zdup [64][256] + e [64][128] + A [128]
#define SMEM_BYTES ((DIM * 2 * TR + DIM * TC + TR) * 4)

__device__ int    g_idx[N_ROWS];
__device__ float  g_A[N_ROWS];
__device__ float  g_B[N_CODES];
__device__ float  g_embT[DIM * N_CODES];
__device__ double g_partial[2048];

__device__ __forceinline__ unsigned long long pack2(float lo, float hi) {
    unsigned long long r;
    asm("mov.b64 %0, {%1, %2};" : "=l"(r) : "f"(lo), "f"(hi));
    return r;
}
__device__ __forceinline__ void unpack2(unsigned long long v, float& lo, float& hi) {
    asm("mov.b64 {%0, %1}, %2;" : "=f"(lo), "=f"(hi) : "l"(v));
}
__device__ __forceinline__ void fma2(unsigned long long& d, unsigned long long a, unsigned long long b) {
    asm("fma.rn.f32x2 %0, %1, %2, %0;" : "+l"(d) : "l"(a), "l"(b));
}

// ---------------------------------------------------------------------------
// Prologue: embT transpose (coalesced writes), A = ||z||^2, B = ||e||^2
// ---------------------------------------------------------------------------
__global__ void vq_prep(const float* __restrict__ z, const float* __restrict__ emb) {
    int t = blockIdx.x * blockDim.x + threadIdx.x;
    if (t < DIM * N_CODES) {
        // embT[c][j] = emb[j][c]; t = c*8192 + j -> coalesced write, L2-hot read
        int c = t >> 13;
        int j = t & 8191;
        g_embT[t] = __ldg(emb + j * DIM + c);
    }
    if (t < N_ROWS) {
        int b = t >> 12, hw = t & 4095;
        const float* zp = z + b * ZB + hw;
        float s = 0.f;
#pragma unroll
        for (int c = 0; c < DIM; c++) {
            float v = zp[c * HW];
            s = __fmaf_rn(v, v, s);
        }
        g_A[t] = s;
    }
    if (t < N_CODES) {
        const float4* ep = (const float4*)(emb + t * DIM);
        float s = 0.f;
#pragma unroll
        for (int i = 0; i < 16; i++) {
            float4 v = ep[i];
            s = __fmaf_rn(v.x, v.x, s);
            s = __fmaf_rn(v.y, v.y, s);
            s = __fmaf_rn(v.z, v.z, s);
            s = __fmaf_rn(v.w, v.w, s);
        }
        g_B[t] = s;
    }
}

// ---------------------------------------------------------------------------
// Main: fused distance GEMM + argmin.
// 256 threads (16 tx x 16 ty), thread tile = 8 rows x 8 codes.
// Code set per thread: {tx*4..tx*4+3} and {64+tx*4..64+tx*4+3} within each
// 128-code chunk -> ea/eb LDS.128 are contiguous across tx lanes (conflict-free).
// z tile duplicated in smem so the f32x2 outer product needs no per-k packing.
// ---------------------------------------------------------------------------
__global__ __launch_bounds__(256, 2) void vq_argmin(const float* __restrict__ z,
                                                    float* __restrict__ outF) {
    extern __shared__ float sm[];
    float* zshd = sm;                        // [64][256]  row-duplicated z (64KB)
    float* esh  = sm + DIM * 2 * TR;         // [64][128]  e chunk, k-major (32KB)
    float* ash  = sm + DIM * 2 * TR + DIM * TC;  // [128]  row norms

    int tid = threadIdx.x;
    int tx = tid & 15, ty = tid >> 4;
    int row0 = blockIdx.x * TR;
    int bb = row0 >> 12, hw0 = row0 & 4095;
    const float* zb = z + bb * ZB + hw0;

    // Load z tile [64 k][128 r], duplicated: zshd[k][2r]=zshd[k][2r+1]=z
#pragma unroll
    for (int i = 0; i < 8; i++) {
        int q = tid + i * 256;               // 2048 float4s
        int c = q >> 5;
        int r4 = (q & 31) << 2;
        float4 v = *(const float4*)(zb + c * HW + r4);
        float2* dst = (float2*)(zshd + c * (2 * TR) + r4 * 2);
        dst[0] = make_float2(v.x, v.x);
        dst[1] = make_float2(v.y, v.y);
        dst[2] = make_float2(v.z, v.z);
        dst[3] = make_float2(v.w, v.w);
    }
    if (tid < 128) ash[tid] = g_A[row0 + tid];

    // A fragment held as 8 scalar floats (packed only in epilogue)
    float Ar[8];
    {
        const float4* ap = (const float4*)(g_A + row0 + ty * 8);
        float4 a0 = ap[0], a1 = ap[1];
        Ar[0] = a0.x; Ar[1] = a0.y; Ar[2] = a0.z; Ar[3] = a0.w;
        Ar[4] = a1.x; Ar[5] = a1.y; Ar[6] = a1.z; Ar[7] = a1.w;
    }

    float best[8];
    int bestj[8];
#pragma unroll
    for (int u = 0; u < 8; u++) { best[u] = __int_as_float(0x7f800000); bestj[u] = 0; }

    for (int ch = 0; ch < NCHUNK; ch++) {
        __syncthreads();
        // Load e chunk (k-major, pre-transposed): coalesced, conflict-free stores
#pragma unroll
        for (int i = 0; i < 8; i++) {
            int q = tid + i * 256;           // 2048 float4s
            int c = q >> 5;
            int j4 = (q & 31) << 2;
            *(float4*)(esh + c * TC + j4) =
                *(const float4*)(g_embT + c * N_CODES + ch * TC + j4);
        }
        __syncthreads();

        unsigned long long acc[8][4];
#pragma unroll
        for (int u = 0; u < 8; u++)
#pragma unroll
            for (int p = 0; p < 4; p++) acc[u][p] = 0ull;

#pragma unroll 8
        for (int k = 0; k < DIM; k++) {
            const ulonglong2* zp = (const ulonglong2*)(zshd + k * (2 * TR) + ty * 16);
            ulonglong2 za = zp[0], zc = zp[1], zd = zp[2], ze = zp[3];
            const ulonglong2* ep = (const ulonglong2*)(esh + k * TC + tx * 4);
            ulonglong2 ea = ep[0];       // codes tx*4 .. tx*4+3
            ulonglong2 eb = ep[16];      // codes 64+tx*4 .. 64+tx*4+3

            fma2(acc[0][0], za.x, ea.x); fma2(acc[0][1], za.x, ea.y);
            fma2(acc[0][2], za.x, eb.x); fma2(acc[0][3], za.x, eb.y);
            fma2(acc[1][0], za.y, ea.x); fma2(acc[1][1], za.y, ea.y);
            fma2(acc[1][2], za.y, eb.x); fma2(acc[1][3], za.y, eb.y);
            fma2(acc[2][0], zc.x, ea.x); fma2(acc[2][1], zc.x, ea.y);
            fma2(acc[2][2], zc.x, eb.x); fma2(acc[2][3], zc.x, eb.y);
            fma2(acc[3][0], zc.y, ea.x); fma2(acc[3][1], zc.y, ea.y);
            fma2(acc[3][2], zc.y, eb.x); fma2(acc[3][3], zc.y, eb.y);
            fma2(acc[4][0], zd.x, ea.x); fma2(acc[4][1], zd.x, ea.y);
            fma2(acc[4][2], zd.x, eb.x); fma2(acc[4][3], zd.x, eb.y);
            fma2(acc[5][0], zd.y, ea.x); fma2(acc[5][1], zd.y, ea.y);
            fma2(acc[5][2], zd.y, eb.x); fma2(acc[5][3], zd.y, eb.y);
            fma2(acc[6][0], ze.x, ea.x); fma2(acc[6][1], ze.x, ea.y);
            fma2(acc[6][2], ze.x, eb.x); fma2(acc[6][3], ze.x, eb.y);
            fma2(acc[7][0], ze.y, ea.x); fma2(acc[7][1], ze.y, ea.y);
            fma2(acc[7][2], ze.y, eb.x); fma2(acc[7][3], ze.y, eb.y);
        }

        // Epilogue: d = fl(fl(A + B) - fl(2*dot)), running argmin (strict <)
        unsigned long long Bp[4];
        {
            float4 b0 = *(const float4*)(g_B + ch * TC + tx * 4);
            float4 b1 = *(const float4*)(g_B + ch * TC + 64 + tx * 4);
            Bp[0] = pack2(b0.x, b0.y); Bp[1] = pack2(b0.z, b0.w);
            Bp[2] = pack2(b1.x, b1.y); Bp[3] = pack2(b1.z, b1.w);
        }
        const unsigned long long neg1 = pack2(-1.0f, -1.0f);
        const unsigned long long two2 = pack2(2.0f, 2.0f);
        int jb0 = ch * TC + tx * 4;          // p=0,1
        int jb1 = jb0 + 64;                  // p=2,3

#pragma unroll
        for (int u = 0; u < 8; u++) {
            unsigned long long Au = pack2(Ar[u], Ar[u]);
#pragma unroll
            for (int p = 0; p < 4; p++) {
                unsigned long long tt, mm, dd;
                asm("add.rn.f32x2 %0, %1, %2;" : "=l"(tt) : "l"(Au), "l"(Bp[p]));
                asm("mul.rn.f32x2 %0, %1, %2;" : "=l"(mm) : "l"(acc[u][p]), "l"(two2));
                asm("fma.rn.f32x2 %0, %1, %2, %3;" : "=l"(dd) : "l"(mm), "l"(neg1), "l"(tt));
                float d0, d1;
                unpack2(dd, d0, d1);
                int j0 = (p < 2 ? jb0 + 2 * p : jb1 + 2 * (p - 2));
                if (d0 < best[u]) { best[u] = d0; bestj[u] = j0; }
                if (d1 < best[u]) { best[u] = d1; bestj[u] = j0 + 1; }
            }
        }
    }

    // Cross-thread reduction per row (16 candidates), tie -> smaller j
    __syncthreads();
    float* cd = esh;                    // [16][128]
    int*   cj = (int*)(esh + 16 * 128); // [16][128]
#pragma unroll
    for (int u = 0; u < 8; u++) {
        int r = ty * 8 + u;
        cd[tx * 128 + r] = best[u];
        cj[tx * 128 + r] = bestj[u];
    }
    __syncthreads();
    if (tid < 128) {
        int r = tid;
        float bd = cd[r];
        int bj = cj[r];
#pragma unroll
        for (int t = 1; t < 16; t++) {
            float d = cd[t * 128 + r];
            int j = cj[t * 128 + r];
            if (d < bd || (d == bd && j < bj)) { bd = d; bj = j; }
        }
        int row = row0 + r;
        g_idx[row] = bj;
        outF[1 + NELEM + row] = (float)bj;
    }
}

// ---------------------------------------------------------------------------
// Output: z_q straight-through (fl(z + fl(e - z))) + loss partials
// ---------------------------------------------------------------------------
__global__ void vq_out(const float* __restrict__ z, const float* __restrict__ emb,
                       float* __restrict__ outF) {
    int t = blockIdx.x * 1024 + threadIdx.x;
    int c = (t >> 12) & 63;
    int n = ((t >> 18) << 12) | (t & 4095);
    int idx = g_idx[n];
    float zv = z[t];
    float e = emb[idx * 64 + c];
    float d1 = __fsub_rn(e, zv);
    outF[1 + t] = __fadd_rn(zv, d1);
    double s = (double)__fmul_rn(d1, d1);
#pragma unroll
    for (int o = 16; o; o >>= 1) s += __shfl_down_sync(0xffffffffu, s, o);
    __shared__ double ws[32];
    int lane = threadIdx.x & 31, w = threadIdx.x >> 5;
    if (lane == 0) ws[w] = s;
    __syncthreads();
    if (w == 0) {
        double v = ws[lane];
#pragma unroll
        for (int o = 16; o; o >>= 1) v += __shfl_down_sync(0xffffffffu, v, o);
        if (lane == 0) g_partial[blockIdx.x] = v;
    }
}

// Deterministic final reduce + loss = fl(m + fl(0.25*m))
__global__ void vq_loss(float* __restrict__ outF) {
    __shared__ double sh[256];
    double s = 0.0;
    for (int i = threadIdx.x; i < 2048; i += 256) s += g_partial[i];
    sh[threadIdx.x] = s;
    __syncthreads();
    for (int st = 128; st; st >>= 1) {
        if (threadIdx.x < st) sh[threadIdx.x] += sh[threadIdx.x + st];
        __syncthreads();
    }
    if (threadIdx.x == 0) {
        float m = (float)(sh[0] / (double)NELEM);
        outF[0] = __fadd_rn(m, __fmul_rn(0.25f, m));
    }
}

extern "C" void kernel_launch(void* const* d_in, const int* in_sizes, int n_in,
                              void* d_out, int out_size) {
    const float* z = (const float*)d_in[0];
    const float* emb = (const float*)d_in[1];
    float* out = (float*)d_out;

    cudaFuncSetAttribute(vq_argmin, cudaFuncAttributeMaxDynamicSharedMemorySize, SMEM_BYTES);

    vq_prep<<<2048, 256>>>(z, emb);
    vq_argmin<<<N_ROWS / TR, 256, SMEM_BYTES>>>(z, out);
    vq_out<<<2048, 1024>>>(z, emb, out);
    vq_loss<<<1, 256>>>(out);
}

// round 4
// speedup vs baseline: 2.2171x; 2.0519x over previous
#include <cuda_runtime.h>
#include <cuda_bf16.h>
#include <cstdint>

#define N_ROWS 32768
#define N_CODES 8192
#define DIM 64
#define HW 4096
#define ZB 262144
#define NELEM 2097152
#define NCH 64
#define TCODES 128
#define CAP (1 << 22)
#define HMARGIN 4.0e-4f

__device__ int                g_idx[N_ROWS];
__device__ float              g_A[N_ROWS];
__device__ float              g_B[N_CODES];
__device__ float              g_zT[N_ROWS * DIM];
__device__ __nv_bfloat16      g_zbf[N_ROWS * DIM];
__device__ __nv_bfloat16      g_ebf[N_CODES * DIM];
__device__ unsigned long long g_key[N_ROWS];
__device__ unsigned int       g_cand[CAP];
__device__ int                g_cnt;
__device__ double             g_partial[2048];

__device__ __forceinline__ uint32_t smem_u32(const void* p) {
    uint32_t a;
    asm("{ .reg .u64 t; cvta.to.shared.u64 t, %1; cvt.u32.u64 %0, t; }" : "=r"(a) : "l"(p));
    return a;
}
__device__ __forceinline__ void cp_async16(uint32_t dst, const void* src) {
    asm volatile("cp.async.cg.shared.global [%0], [%1], 16;" :: "r"(dst), "l"(src) : "memory");
}
#define CP_COMMIT() asm volatile("cp.async.commit_group;" ::: "memory")
#define CP_WAIT1()  asm volatile("cp.async.wait_group 1;" ::: "memory")
#define CP_WAIT0()  asm volatile("cp.async.wait_group 0;" ::: "memory")

__device__ __forceinline__ void mma16816(float& c0, float& c1, float& c2, float& c3,
                                         uint32_t a0, uint32_t a1, uint32_t a2, uint32_t a3,
                                         uint32_t b0, uint32_t b1) {
    asm volatile(
        "mma.sync.aligned.m16n8k16.row.col.f32.bf16.bf16.f32 "
        "{%0,%1,%2,%3}, {%4,%5,%6,%7}, {%8,%9}, {%0,%1,%2,%3};"
        : "+f"(c0), "+f"(c1), "+f"(c2), "+f"(c3)
        : "r"(a0), "r"(a1), "r"(a2), "r"(a3), "r"(b0), "r"(b1));
}

// ---------------------------------------------------------------------------
// Transpose z -> zT (f32 row-major), zbf (bf16), A = ||z||^2 (ascending-c fma)
// ---------------------------------------------------------------------------
__global__ void vq_transpose(const float* __restrict__ z) {
    __shared__ float sm[64][65];
    int b = blockIdx.x >> 6;
    int hw0 = (blockIdx.x & 63) << 6;
    int cc = threadIdx.x >> 6, hh = threadIdx.x & 63;
    const float* zb = z + b * ZB + hw0;
#pragma unroll
    for (int cq = 0; cq < 16; cq++) {
        int c = cq * 4 + cc;
        sm[hh][c] = zb[c * HW + hh];
    }
    __syncthreads();
#pragma unroll
    for (int rq = 0; rq < 16; rq++) {
        int r = rq * 4 + cc;
        int n = b * 4096 + hw0 + r;
        float v = sm[r][hh];
        g_zT[n * DIM + hh] = v;
        g_zbf[n * DIM + hh] = __float2bfloat16(v);
    }
    if (threadIdx.x < 64) {
        int r = threadIdx.x;
        float s = 0.f;
#pragma unroll
        for (int c = 0; c < DIM; c++) s = __fmaf_rn(sm[r][c], sm[r][c], s);
        g_A[b * 4096 + hw0 + r] = s;
    }
}

__global__ void vq_prep(const float* __restrict__ emb) {
    int t = blockIdx.x * blockDim.x + threadIdx.x;
    if (t < N_CODES * DIM) g_ebf[t] = __float2bfloat16(emb[t]);
    if (t < N_ROWS) g_key[t] = 0xFFFFFFFFFFFFFFFFull;
    if (t == 0) g_cnt = 0;
    if (t < N_CODES) {
        const float4* ep = (const float4*)(emb + t * DIM);
        float s = 0.f;
#pragma unroll
        for (int i = 0; i < 16; i++) {
            float4 v = ep[i];
            s = __fmaf_rn(v.x, v.x, s);
            s = __fmaf_rn(v.y, v.y, s);
            s = __fmaf_rn(v.z, v.z, s);
            s = __fmaf_rn(v.w, v.w, s);
        }
        g_B[t] = s;
    }
}

// ---------------------------------------------------------------------------
// Filter: bf16 mma.sync dots, per-row running max + candidate collection.
// CTA 256 thr / 8 warps / 128 rows; warp = 16 rows. e in 128-code chunks,
// cp.async double-buffered smem, SW128 swizzle, direct LDS b-frags.
// ---------------------------------------------------------------------------
#define SMEM_MMA (2 * TCODES * 128)   // 32KB: two 16KB e buffers

__global__ __launch_bounds__(256, 2) void vq_mma(void) {
    extern __shared__ char smc[];
    uint32_t sb = smem_u32(smc);
    int tid = threadIdx.x;
    int wid = tid >> 5, lane = tid & 31;
    int row0 = blockIdx.x * 128;
    int g = lane >> 2, q = lane & 3;

    // A fragments: rows rw+g, rw+g+8; k in 4 steps of 16
    int rw = row0 + wid * 16;
    int row_a = rw + g, row_b = row_a + 8;
    uint32_t a[4][4];
#pragma unroll
    for (int ks = 0; ks < 4; ks++) {
        const char* pa = (const char*)(g_zbf + row_a * DIM + ks * 16 + q * 2);
        const char* pb = (const char*)(g_zbf + row_b * DIM + ks * 16 + q * 2);
        a[ks][0] = *(const uint32_t*)pa;
        a[ks][1] = *(const uint32_t*)pb;
        a[ks][2] = *(const uint32_t*)(pa + 16);
        a[ks][3] = *(const uint32_t*)(pb + 16);
    }

    // b-frag smem addressing (swizzled): row = n0 + g, byte = ks*32 + q*4
    uint32_t brow_base = (uint32_t)g * 128;
    uint32_t bxor = (uint32_t)g << 4;

    // prefetch chunks 0 and 1
#pragma unroll
    for (int pc = 0; pc < 2; pc++) {
#pragma unroll
        for (int i = 0; i < 4; i++) {
            int s = tid + i * 256;               // 1024 16B segs
            int r = s >> 3, seg = s & 7;
            uint32_t off = (uint32_t)(r * 128 + seg * 16);
            uint32_t dst = sb + pc * 16384 + (off ^ ((off >> 3) & 0x70));
            cp_async16(dst, g_ebf + (pc * TCODES + r) * DIM + seg * 8);
        }
        CP_COMMIT();
    }

    const float NEGINF = -__int_as_float(0x7f800000);
    float run0 = NEGINF, run1 = NEGINF;

    for (int c = 0; c < NCH; c++) {
        if (c < NCH - 1) CP_WAIT1(); else CP_WAIT0();
        __syncthreads();

        uint32_t ebase = sb + (c & 1) * 16384;
        float acc[16][4];

#pragma unroll
        for (int t = 0; t < 16; t++) {
            float c0 = 0.f, c1 = 0.f, c2 = 0.f, c3 = 0.f;
            uint32_t rbase = ebase + (uint32_t)(t * 8) * 128 + brow_base;
#pragma unroll
            for (int ks = 0; ks < 4; ks++) {
                uint32_t off = ((uint32_t)(ks * 32) + q * 4) ^ bxor;
                uint32_t b0, b1;
                asm volatile("ld.shared.b32 %0, [%1];" : "=r"(b0) : "r"(rbase + off));
                asm volatile("ld.shared.b32 %0, [%1];" : "=r"(b1) : "r"(rbase + (off ^ 16)));
                mma16816(c0, c1, c2, c3, a[ks][0], a[ks][1], a[ks][2], a[ks][3], b0, b1);
            }
            acc[t][0] = c0; acc[t][1] = c1; acc[t][2] = c2; acc[t][3] = c3;
        }

        __syncthreads();
        if (c + 2 < NCH) {
#pragma unroll
            for (int i = 0; i < 4; i++) {
                int s = tid + i * 256;
                int r = s >> 3, seg = s & 7;
                uint32_t off = (uint32_t)(r * 128 + seg * 16);
                uint32_t dst = sb + (c & 1) * 16384 + (off ^ ((off >> 3) & 0x70));
                cp_async16(dst, g_ebf + ((c + 2) * TCODES + r) * DIM + seg * 8);
            }
            CP_COMMIT();
        }

        // per-row chunk max
        float m0 = NEGINF, m1 = NEGINF;
#pragma unroll
        for (int t = 0; t < 16; t++) {
            m0 = fmaxf(m0, fmaxf(acc[t][0], acc[t][1]));
            m1 = fmaxf(m1, fmaxf(acc[t][2], acc[t][3]));
        }
        m0 = fmaxf(m0, __shfl_xor_sync(0xffffffffu, m0, 1));
        m0 = fmaxf(m0, __shfl_xor_sync(0xffffffffu, m0, 2));
        m1 = fmaxf(m1, __shfl_xor_sync(0xffffffffu, m1, 1));
        m1 = fmaxf(m1, __shfl_xor_sync(0xffffffffu, m1, 2));
        run0 = fmaxf(run0, m0);
        run1 = fmaxf(run1, m1);
        float thr0 = run0 - HMARGIN, thr1 = run1 - HMARGIN;

        int j0 = c * TCODES + q * 2;
#pragma unroll
        for (int t = 0; t < 16; t++) {
            int j = j0 + t * 8;
            if (acc[t][0] >= thr0) {
                int pos = atomicAdd(&g_cnt, 1);
                if (pos < CAP) g_cand[pos] = ((unsigned)row_a << 13) | (unsigned)j;
            }
            if (acc[t][1] >= thr0) {
                int pos = atomicAdd(&g_cnt, 1);
                if (pos < CAP) g_cand[pos] = ((unsigned)row_a << 13) | (unsigned)(j + 1);
            }
            if (acc[t][2] >= thr1) {
                int pos = atomicAdd(&g_cnt, 1);
                if (pos < CAP) g_cand[pos] = ((unsigned)row_b << 13) | (unsigned)j;
            }
            if (acc[t][3] >= thr1) {
                int pos = atomicAdd(&g_cnt, 1);
                if (pos < CAP) g_cand[pos] = ((unsigned)row_b << 13) | (unsigned)(j + 1);
            }
        }
    }
}

// ---------------------------------------------------------------------------
// Exact recheck: reference-matching fp32 d; atomicMin key = (d_bits<<13)|j
// ---------------------------------------------------------------------------
__global__ void vq_exact(const float* __restrict__ emb) {
    int cnt = g_cnt;
    if (cnt > CAP) cnt = CAP;
    for (int i = blockIdx.x * blockDim.x + threadIdx.x; i < cnt; i += gridDim.x * blockDim.x) {
        unsigned u = g_cand[i];
        int n = u >> 13;
        int j = u & 8191;
        const float* zr = g_zT + n * DIM;
        const float* er = emb + j * DIM;
        float dot = 0.f;
#pragma unroll
        for (int cc = 0; cc < DIM; cc++) dot = __fmaf_rn(zr[cc], er[cc], dot);
        float d = __fsub_rn(__fadd_rn(g_A[n], g_B[j]), __fmul_rn(2.0f, dot));
        unsigned long long key = ((unsigned long long)__float_as_uint(d) << 13) | (unsigned)j;
        atomicMin(&g_key[n], key);
    }
}

__global__ void vq_finalize(float* __restrict__ outF) {
    int t = blockIdx.x * blockDim.x + threadIdx.x;
    if (t < N_ROWS) {
        int j = (int)(g_key[t] & 8191ull);
        g_idx[t] = j;
        outF[1 + NELEM + t] = (float)j;
    }
}

__global__ void vq_out(const float* __restrict__ z, const float* __restrict__ emb,
                       float* __restrict__ outF) {
    int t = blockIdx.x * 1024 + threadIdx.x;
    int c = (t >> 12) & 63;
    int n = ((t >> 18) << 12) | (t & 4095);
    int idx = g_idx[n];
    float zv = z[t];
    float e = emb[idx * 64 + c];
    float d1 = __fsub_rn(e, zv);
    outF[1 + t] = __fadd_rn(zv, d1);
    double s = (double)__fmul_rn(d1, d1);
#pragma unroll
    for (int o = 16; o; o >>= 1) s += __shfl_down_sync(0xffffffffu, s, o);
    __shared__ double ws[32];
    int lane = threadIdx.x & 31, w = threadIdx.x >> 5;
    if (lane == 0) ws[w] = s;
    __syncthreads();
    if (w == 0) {
        double v = ws[lane];
#pragma unroll
        for (int o = 16; o; o >>= 1) v += __shfl_down_sync(0xffffffffu, v, o);
        if (lane == 0) g_partial[blockIdx.x] = v;
    }
}

__global__ void vq_loss(float* __restrict__ outF) {
    __shared__ double sh[256];
    double s = 0.0;
    for (int i = threadIdx.x; i < 2048; i += 256) s += g_partial[i];
    sh[threadIdx.x] = s;
    __syncthreads();
    for (int st = 128; st; st >>= 1) {
        if (threadIdx.x < st) sh[threadIdx.x] += sh[threadIdx.x + st];
        __syncthreads();
    }
    if (threadIdx.x == 0) {
        float m = (float)(sh[0] / (double)NELEM);
        outF[0] = __fadd_rn(m, __fmul_rn(0.25f, m));
    }
}

extern "C" void kernel_launch(void* const* d_in, const int* in_sizes, int n_in,
                              void* d_out, int out_size) {
    const float* z = (const float*)d_in[0];
    const float* emb = (const float*)d_in[1];
    float* out = (float*)d_out;

    cudaFuncSetAttribute(vq_mma, cudaFuncAttributeMaxDynamicSharedMemorySize, SMEM_MMA);

    vq_transpose<<<512, 256>>>(z);
    vq_prep<<<2048, 256>>>(emb);
    vq_mma<<<N_ROWS / 128, 256, SMEM_MMA>>>();
    vq_exact<<<512, 256>>>(emb);
    vq_finalize<<<32, 1024>>>(out);
    vq_out<<<2048, 1024>>>(z, emb, out);
    vq_loss<<<1, 256>>>(out);
}

// round 5
// speedup vs baseline: 2.6276x; 1.1851x over previous
#include <cuda_runtime.h>
#include <cuda_bf16.h>
#include <cstdint>

#define N_ROWS 32768
#define N_CODES 8192
#define DIM 64
#define HW 4096
#define ZB 262144
#define NELEM 2097152
#define NCH 64
#define TCODES 128
#define CAP (1 << 22)
#define HMARGIN 4.0e-4f

__device__ int                g_idx[N_ROWS];
__device__ float              g_A[N_ROWS];
__device__ float              g_B[N_CODES];
__device__ float              g_zT[N_ROWS * DIM];
__device__ __nv_bfloat16      g_zbf[N_ROWS * DIM];
__device__ __nv_bfloat16      g_ebf[N_CODES * DIM];
__device__ unsigned long long g_key[N_ROWS];
__device__ unsigned int       g_cand[CAP];
__device__ int                g_cnt;
__device__ double             g_partial[2048];

__device__ __forceinline__ uint32_t smem_u32(const void* p) {
    uint32_t a;
    asm("{ .reg .u64 t; cvta.to.shared.u64 t, %1; cvt.u32.u64 %0, t; }" : "=r"(a) : "l"(p));
    return a;
}
__device__ __forceinline__ void cp_async16(uint32_t dst, const void* src) {
    asm volatile("cp.async.cg.shared.global [%0], [%1], 16;" :: "r"(dst), "l"(src) : "memory");
}
#define CP_COMMIT() asm volatile("cp.async.commit_group;" ::: "memory")
#define CP_WAIT1()  asm volatile("cp.async.wait_group 1;" ::: "memory")
#define CP_WAIT0()  asm volatile("cp.async.wait_group 0;" ::: "memory")

__device__ __forceinline__ void mma16816(float& c0, float& c1, float& c2, float& c3,
                                         uint32_t a0, uint32_t a1, uint32_t a2, uint32_t a3,
                                         uint32_t b0, uint32_t b1) {
    asm volatile(
        "mma.sync.aligned.m16n8k16.row.col.f32.bf16.bf16.f32 "
        "{%0,%1,%2,%3}, {%4,%5,%6,%7}, {%8,%9}, {%0,%1,%2,%3};"
        : "+f"(c0), "+f"(c1), "+f"(c2), "+f"(c3)
        : "r"(a0), "r"(a1), "r"(a2), "r"(a3), "r"(b0), "r"(b1));
}
__device__ __forceinline__ void ldmatrix_x4(uint32_t& r0, uint32_t& r1, uint32_t& r2,
                                            uint32_t& r3, uint32_t addr) {
    asm volatile("ldmatrix.sync.aligned.m8n8.x4.shared.b16 {%0,%1,%2,%3}, [%4];"
                 : "=r"(r0), "=r"(r1), "=r"(r2), "=r"(r3) : "r"(addr));
}

// ---------------------------------------------------------------------------
// Transpose z -> zT (f32 row-major), zbf (bf16), A = ||z||^2 (ascending-c fma)
// ---------------------------------------------------------------------------
__global__ void vq_transpose(const float* __restrict__ z) {
    __shared__ float sm[64][65];
    int b = blockIdx.x >> 6;
    int hw0 = (blockIdx.x & 63) << 6;
    int cc = threadIdx.x >> 6, hh = threadIdx.x & 63;
    const float* zb = z + b * ZB + hw0;
#pragma unroll
    for (int cq = 0; cq < 16; cq++) {
        int c = cq * 4 + cc;
        sm[hh][c] = zb[c * HW + hh];
    }
    __syncthreads();
#pragma unroll
    for (int rq = 0; rq < 16; rq++) {
        int r = rq * 4 + cc;
        int n = b * 4096 + hw0 + r;
        float v = sm[r][hh];
        g_zT[n * DIM + hh] = v;
        g_zbf[n * DIM + hh] = __float2bfloat16(v);
    }
    if (threadIdx.x < 64) {
        int r = threadIdx.x;
        float s = 0.f;
#pragma unroll
        for (int c = 0; c < DIM; c++) s = __fmaf_rn(sm[r][c], sm[r][c], s);
        g_A[b * 4096 + hw0 + r] = s;
    }
}

__global__ void vq_prep(const float* __restrict__ emb) {
    int t = blockIdx.x * blockDim.x + threadIdx.x;
    if (t < N_CODES * DIM) g_ebf[t] = __float2bfloat16(emb[t]);
    if (t < N_ROWS) g_key[t] = 0xFFFFFFFFFFFFFFFFull;
    if (t == 0) g_cnt = 0;
    if (t < N_CODES) {
        const float4* ep = (const float4*)(emb + t * DIM);
        float s = 0.f;
#pragma unroll
        for (int i = 0; i < 16; i++) {
            float4 v = ep[i];
            s = __fmaf_rn(v.x, v.x, s);
            s = __fmaf_rn(v.y, v.y, s);
            s = __fmaf_rn(v.z, v.z, s);
            s = __fmaf_rn(v.w, v.w, s);
        }
        g_B[t] = s;
    }
}

// ---------------------------------------------------------------------------
// Filter: bf16 mma.sync dots + running-max candidate collection.
// CTA 256 thr / 8 warps / 128 rows; warp = 16 rows x 128 codes per chunk.
// B-frags via ldmatrix.x4 (swizzled), cp.async double-buffered e tiles.
// ---------------------------------------------------------------------------
#define SMEM_MMA (2 * TCODES * 128)

__global__ __launch_bounds__(256, 2) void vq_mma(void) {
    extern __shared__ char smc[];
    uint32_t sb = smem_u32(smc);
    int tid = threadIdx.x;
    int wid = tid >> 5, lane = tid & 31;
    int row0 = blockIdx.x * 128;
    int g = lane >> 2, q = lane & 3;

    // A fragments: rows rw+g, rw+g+8; k in 4 steps of 16
    int rw = row0 + wid * 16;
    int row_a = rw + g, row_b = row_a + 8;
    uint32_t a[4][4];
#pragma unroll
    for (int ks = 0; ks < 4; ks++) {
        const char* pa = (const char*)(g_zbf + row_a * DIM + ks * 16 + q * 2);
        const char* pb = (const char*)(g_zbf + row_b * DIM + ks * 16 + q * 2);
        a[ks][0] = *(const uint32_t*)pa;
        a[ks][1] = *(const uint32_t*)pb;
        a[ks][2] = *(const uint32_t*)(pa + 16);
        a[ks][3] = *(const uint32_t*)(pb + 16);
    }

    // ldmatrix per-lane addressing: row = 8t + (lane&7), seg = ld*4 + (lane>>3)
    // swizzled byte = row*128 + (seg ^ (row&7))*16
    uint32_t r8 = (uint32_t)(lane & 7);
    uint32_t h2 = (uint32_t)(lane >> 3);
    uint32_t seg1 = (h2 ^ r8) * 16;          // first ldmatrix: segs 0..3
    uint32_t seg2 = ((4 + h2) ^ r8) * 16;    // second ldmatrix: segs 4..7
    uint32_t lrow = r8 * 128;

    // prefetch chunks 0 and 1
#pragma unroll
    for (int pc = 0; pc < 2; pc++) {
#pragma unroll
        for (int i = 0; i < 4; i++) {
            int s = tid + i * 256;
            int r = s >> 3, seg = s & 7;
            uint32_t off = (uint32_t)(r * 128 + seg * 16);
            uint32_t dst = sb + pc * 16384 + (off ^ ((off >> 3) & 0x70));
            cp_async16(dst, g_ebf + (pc * TCODES + r) * DIM + seg * 8);
        }
        CP_COMMIT();
    }

    const float NEGINF = -__int_as_float(0x7f800000);
    float run0 = NEGINF, run1 = NEGINF;

    for (int c = 0; c < NCH; c++) {
        if (c < NCH - 1) CP_WAIT1(); else CP_WAIT0();
        __syncthreads();

        uint32_t ebase = sb + (c & 1) * 16384 + lrow;
        float acc[16][4];

#pragma unroll
        for (int t = 0; t < 16; t++) {
            uint32_t tb = ebase + (uint32_t)t * 1024;
            uint32_t b0, b1, b2, b3, b4, b5, b6, b7;
            ldmatrix_x4(b0, b1, b2, b3, tb + seg1);
            ldmatrix_x4(b4, b5, b6, b7, tb + seg2);
            float c0 = 0.f, c1 = 0.f, c2 = 0.f, c3 = 0.f;
            mma16816(c0, c1, c2, c3, a[0][0], a[0][1], a[0][2], a[0][3], b0, b1);
            mma16816(c0, c1, c2, c3, a[1][0], a[1][1], a[1][2], a[1][3], b2, b3);
            mma16816(c0, c1, c2, c3, a[2][0], a[2][1], a[2][2], a[2][3], b4, b5);
            mma16816(c0, c1, c2, c3, a[3][0], a[3][1], a[3][2], a[3][3], b6, b7);
            acc[t][0] = c0; acc[t][1] = c1; acc[t][2] = c2; acc[t][3] = c3;
        }

        __syncthreads();
        if (c + 2 < NCH) {
#pragma unroll
            for (int i = 0; i < 4; i++) {
                int s = tid + i * 256;
                int r = s >> 3, seg = s & 7;
                uint32_t off = (uint32_t)(r * 128 + seg * 16);
                uint32_t dst = sb + (c & 1) * 16384 + (off ^ ((off >> 3) & 0x70));
                cp_async16(dst, g_ebf + ((c + 2) * TCODES + r) * DIM + seg * 8);
            }
            CP_COMMIT();
        }

        // per-row chunk max
        float m0 = NEGINF, m1 = NEGINF;
#pragma unroll
        for (int t = 0; t < 16; t++) {
            m0 = fmaxf(m0, fmaxf(acc[t][0], acc[t][1]));
            m1 = fmaxf(m1, fmaxf(acc[t][2], acc[t][3]));
        }
        m0 = fmaxf(m0, __shfl_xor_sync(0xffffffffu, m0, 1));
        m0 = fmaxf(m0, __shfl_xor_sync(0xffffffffu, m0, 2));
        m1 = fmaxf(m1, __shfl_xor_sync(0xffffffffu, m1, 1));
        m1 = fmaxf(m1, __shfl_xor_sync(0xffffffffu, m1, 2));
        run0 = fmaxf(run0, m0);
        run1 = fmaxf(run1, m1);
        float thr0 = run0 - HMARGIN, thr1 = run1 - HMARGIN;

        int j0 = c * TCODES + q * 2;
#pragma unroll
        for (int t = 0; t < 16; t++) {
            int j = j0 + t * 8;
            if (acc[t][0] >= thr0) {
                int pos = atomicAdd(&g_cnt, 1);
                if (pos < CAP) g_cand[pos] = ((unsigned)row_a << 13) | (unsigned)j;
            }
            if (acc[t][1] >= thr0) {
                int pos = atomicAdd(&g_cnt, 1);
                if (pos < CAP) g_cand[pos] = ((unsigned)row_a << 13) | (unsigned)(j + 1);
            }
            if (acc[t][2] >= thr1) {
                int pos = atomicAdd(&g_cnt, 1);
                if (pos < CAP) g_cand[pos] = ((unsigned)row_b << 13) | (unsigned)j;
            }
            if (acc[t][3] >= thr1) {
                int pos = atomicAdd(&g_cnt, 1);
                if (pos < CAP) g_cand[pos] = ((unsigned)row_b << 13) | (unsigned)(j + 1);
            }
        }
    }
}

// ---------------------------------------------------------------------------
// Exact recheck: reference-matching fp32 d via float4 loads (same ascending
// x,y,z,w FMA chain as scalar); atomicMin key = (d_bits<<13)|j
// ---------------------------------------------------------------------------
__global__ void vq_exact(const float* __restrict__ emb) {
    int cnt = g_cnt;
    if (cnt > CAP) cnt = CAP;
    for (int i = blockIdx.x * blockDim.x + threadIdx.x; i < cnt; i += gridDim.x * blockDim.x) {
        unsigned u = g_cand[i];
        int n = u >> 13;
        int j = u & 8191;
        const float4* zr = (const float4*)(g_zT + n * DIM);
        const float4* er = (const float4*)(emb + j * DIM);
        float dot = 0.f;
#pragma unroll
        for (int cc = 0; cc < 16; cc++) {
            float4 av = zr[cc];
            float4 bv = er[cc];
            dot = __fmaf_rn(av.x, bv.x, dot);
            dot = __fmaf_rn(av.y, bv.y, dot);
            dot = __fmaf_rn(av.z, bv.z, dot);
            dot = __fmaf_rn(av.w, bv.w, dot);
        }
        float d = __fsub_rn(__fadd_rn(g_A[n], g_B[j]), __fmul_rn(2.0f, dot));
        unsigned long long key = ((unsigned long long)__float_as_uint(d) << 13) | (unsigned)j;
        atomicMin(&g_key[n], key);
    }
}

__global__ void vq_finalize(float* __restrict__ outF) {
    int t = blockIdx.x * blockDim.x + threadIdx.x;
    if (t < N_ROWS) {
        int j = (int)(g_key[t] & 8191ull);
        g_idx[t] = j;
        outF[1 + NELEM + t] = (float)j;
    }
}

__global__ void vq_out(const float* __restrict__ z, const float* __restrict__ emb,
                       float* __restrict__ outF) {
    int t = blockIdx.x * 1024 + threadIdx.x;
    int c = (t >> 12) & 63;
    int n = ((t >> 18) << 12) | (t & 4095);
    int idx = g_idx[n];
    float zv = z[t];
    float e = emb[idx * 64 + c];
    float d1 = __fsub_rn(e, zv);
    outF[1 + t] = __fadd_rn(zv, d1);
    double s = (double)__fmul_rn(d1, d1);
#pragma unroll
    for (int o = 16; o; o >>= 1) s += __shfl_down_sync(0xffffffffu, s, o);
    __shared__ double ws[32];
    int lane = threadIdx.x & 31, w = threadIdx.x >> 5;
    if (lane == 0) ws[w] = s;
    __syncthreads();
    if (w == 0) {
        double v = ws[lane];
#pragma unroll
        for (int o = 16; o; o >>= 1) v += __shfl_down_sync(0xffffffffu, v, o);
        if (lane == 0) g_partial[blockIdx.x] = v;
    }
}

__global__ void vq_loss(float* __restrict__ outF) {
    __shared__ double sh[256];
    double s = 0.0;
    for (int i = threadIdx.x; i < 2048; i += 256) s += g_partial[i];
    sh[threadIdx.x] = s;
    __syncthreads();
    for (int st = 128; st; st >>= 1) {
        if (threadIdx.x < st) sh[threadIdx.x] += sh[threadIdx.x + st];
        __syncthreads();
    }
    if (threadIdx.x == 0) {
        float m = (float)(sh[0] / (double)NELEM);
        outF[0] = __fadd_rn(m, __fmul_rn(0.25f, m));
    }
}

extern "C" void kernel_launch(void* const* d_in, const int* in_sizes, int n_in,
                              void* d_out, int out_size) {
    const float* z = (const float*)d_in[0];
    const float* emb = (const float*)d_in[1];
    float* out = (float*)d_out;

    cudaFuncSetAttribute(vq_mma, cudaFuncAttributeMaxDynamicSharedMemorySize, SMEM_MMA);

    vq_transpose<<<512, 256>>>(z);
    vq_prep<<<2048, 256>>>(emb);
    vq_mma<<<N_ROWS / 128, 256, SMEM_MMA>>>();
    vq_exact<<<512, 256>>>(emb);
    vq_finalize<<<32, 1024>>>(out);
    vq_out<<<2048, 1024>>>(z, emb, out);
    vq_loss<<<1, 256>>>(out);
}

// round 6
// speedup vs baseline: 2.9231x; 1.1124x over previous
#include <cuda_runtime.h>
#include <cuda_bf16.h>
#include <cstdint>

#define N_ROWS 32768
#define N_CODES 8192
#define DIM 64
#define HW 4096
#define ZB 262144
#define NELEM 2097152
#define NCH 64
#define TCODES 128
#define CAP (1 << 22)
#define HMARGIN 4.0e-4f

__device__ int                g_idx[N_ROWS];
__device__ float              g_A[N_ROWS];
__device__ float              g_B[N_CODES];
__device__ float              g_zT[N_ROWS * DIM];
__device__ __nv_bfloat16      g_zbf[N_ROWS * DIM];
__device__ __nv_bfloat16      g_ebf[N_CODES * DIM];
__device__ unsigned long long g_key[N_ROWS];
__device__ unsigned int       g_cand[CAP];
__device__ int                g_cnt;
__device__ double             g_partial[2048];

__device__ __forceinline__ uint32_t smem_u32(const void* p) {
    uint32_t a;
    asm("{ .reg .u64 t; cvta.to.shared.u64 t, %1; cvt.u32.u64 %0, t; }" : "=r"(a) : "l"(p));
    return a;
}
__device__ __forceinline__ void cp_async16(uint32_t dst, const void* src) {
    asm volatile("cp.async.cg.shared.global [%0], [%1], 16;" :: "r"(dst), "l"(src) : "memory");
}
#define CP_COMMIT() asm volatile("cp.async.commit_group;" ::: "memory")
#define CP_WAIT1()  asm volatile("cp.async.wait_group 1;" ::: "memory")
#define CP_WAIT0()  asm volatile("cp.async.wait_group 0;" ::: "memory")

__device__ __forceinline__ void mma16816(float& c0, float& c1, float& c2, float& c3,
                                         uint32_t a0, uint32_t a1, uint32_t a2, uint32_t a3,
                                         uint32_t b0, uint32_t b1) {
    asm volatile(
        "mma.sync.aligned.m16n8k16.row.col.f32.bf16.bf16.f32 "
        "{%0,%1,%2,%3}, {%4,%5,%6,%7}, {%8,%9}, {%0,%1,%2,%3};"
        : "+f"(c0), "+f"(c1), "+f"(c2), "+f"(c3)
        : "r"(a0), "r"(a1), "r"(a2), "r"(a3), "r"(b0), "r"(b1));
}
__device__ __forceinline__ void ldmatrix_x4(uint32_t& r0, uint32_t& r1, uint32_t& r2,
                                            uint32_t& r3, uint32_t addr) {
    asm volatile("ldmatrix.sync.aligned.m8n8.x4.shared.b16 {%0,%1,%2,%3}, [%4];"
                 : "=r"(r0), "=r"(r1), "=r"(r2), "=r"(r3) : "r"(addr));
}

// ---------------------------------------------------------------------------
// Transpose z -> zT (f32 row-major), zbf (bf16), A = ||z||^2 (ascending-c fma)
// ---------------------------------------------------------------------------
__global__ void vq_transpose(const float* __restrict__ z) {
    __shared__ float sm[64][65];
    int b = blockIdx.x >> 6;
    int hw0 = (blockIdx.x & 63) << 6;
    int cc = threadIdx.x >> 6, hh = threadIdx.x & 63;
    const float* zb = z + b * ZB + hw0;
#pragma unroll
    for (int cq = 0; cq < 16; cq++) {
        int c = cq * 4 + cc;
        sm[hh][c] = zb[c * HW + hh];
    }
    __syncthreads();
#pragma unroll
    for (int rq = 0; rq < 16; rq++) {
        int r = rq * 4 + cc;
        int n = b * 4096 + hw0 + r;
        float v = sm[r][hh];
        g_zT[n * DIM + hh] = v;
        g_zbf[n * DIM + hh] = __float2bfloat16(v);
    }
    if (threadIdx.x < 64) {
        int r = threadIdx.x;
        float s = 0.f;
#pragma unroll
        for (int c = 0; c < DIM; c++) s = __fmaf_rn(sm[r][c], sm[r][c], s);
        g_A[b * 4096 + hw0 + r] = s;
    }
}

__global__ void vq_prep(const float* __restrict__ emb) {
    int t = blockIdx.x * blockDim.x + threadIdx.x;
    if (t < N_CODES * DIM) g_ebf[t] = __float2bfloat16(emb[t]);
    if (t < N_ROWS) g_key[t] = 0xFFFFFFFFFFFFFFFFull;
    if (t == 0) g_cnt = 0;
    if (t < N_CODES) {
        const float4* ep = (const float4*)(emb + t * DIM);
        float s = 0.f;
#pragma unroll
        for (int i = 0; i < 16; i++) {
            float4 v = ep[i];
            s = __fmaf_rn(v.x, v.x, s);
            s = __fmaf_rn(v.y, v.y, s);
            s = __fmaf_rn(v.z, v.z, s);
            s = __fmaf_rn(v.w, v.w, s);
        }
        g_B[t] = s;
    }
}

// ---------------------------------------------------------------------------
// Filter: bf16 mma.sync dots + running-max candidate collection.
// CTA 256 thr / 8 warps / 128 rows; warp = 16 rows x 128 codes per chunk.
// ldmatrix B-frags, cp.async double buffer, warp-skip + aggregated atomics.
// ---------------------------------------------------------------------------
#define SMEM_MMA (2 * TCODES * 128)

__global__ __launch_bounds__(256, 2) void vq_mma(void) {
    extern __shared__ char smc[];
    uint32_t sb = smem_u32(smc);
    int tid = threadIdx.x;
    int wid = tid >> 5, lane = tid & 31;
    int row0 = blockIdx.x * 128;
    int g = lane >> 2, q = lane & 3;

    int rw = row0 + wid * 16;
    int row_a = rw + g, row_b = row_a + 8;
    uint32_t a[4][4];
#pragma unroll
    for (int ks = 0; ks < 4; ks++) {
        const char* pa = (const char*)(g_zbf + row_a * DIM + ks * 16 + q * 2);
        const char* pb = (const char*)(g_zbf + row_b * DIM + ks * 16 + q * 2);
        a[ks][0] = *(const uint32_t*)pa;
        a[ks][1] = *(const uint32_t*)pb;
        a[ks][2] = *(const uint32_t*)(pa + 16);
        a[ks][3] = *(const uint32_t*)(pb + 16);
    }

    uint32_t r8 = (uint32_t)(lane & 7);
    uint32_t h2 = (uint32_t)(lane >> 3);
    uint32_t seg1 = (h2 ^ r8) * 16;
    uint32_t seg2 = ((4 + h2) ^ r8) * 16;
    uint32_t lrow = r8 * 128;

#pragma unroll
    for (int pc = 0; pc < 2; pc++) {
#pragma unroll
        for (int i = 0; i < 4; i++) {
            int s = tid + i * 256;
            int r = s >> 3, seg = s & 7;
            uint32_t off = (uint32_t)(r * 128 + seg * 16);
            uint32_t dst = sb + pc * 16384 + (off ^ ((off >> 3) & 0x70));
            cp_async16(dst, g_ebf + (pc * TCODES + r) * DIM + seg * 8);
        }
        CP_COMMIT();
    }

    const float NEGINF = -__int_as_float(0x7f800000);
    float run0 = NEGINF, run1 = NEGINF;

    for (int c = 0; c < NCH; c++) {
        if (c < NCH - 1) CP_WAIT1(); else CP_WAIT0();
        __syncthreads();

        uint32_t ebase = sb + (c & 1) * 16384 + lrow;
        float acc[16][4];

#pragma unroll
        for (int t = 0; t < 16; t++) {
            uint32_t tb = ebase + (uint32_t)t * 1024;
            uint32_t b0, b1, b2, b3, b4, b5, b6, b7;
            ldmatrix_x4(b0, b1, b2, b3, tb + seg1);
            ldmatrix_x4(b4, b5, b6, b7, tb + seg2);
            float c0 = 0.f, c1 = 0.f, c2 = 0.f, c3 = 0.f;
            mma16816(c0, c1, c2, c3, a[0][0], a[0][1], a[0][2], a[0][3], b0, b1);
            mma16816(c0, c1, c2, c3, a[1][0], a[1][1], a[1][2], a[1][3], b2, b3);
            mma16816(c0, c1, c2, c3, a[2][0], a[2][1], a[2][2], a[2][3], b4, b5);
            mma16816(c0, c1, c2, c3, a[3][0], a[3][1], a[3][2], a[3][3], b6, b7);
            acc[t][0] = c0; acc[t][1] = c1; acc[t][2] = c2; acc[t][3] = c3;
        }

        __syncthreads();
        if (c + 2 < NCH) {
#pragma unroll
            for (int i = 0; i < 4; i++) {
                int s = tid + i * 256;
                int r = s >> 3, seg = s & 7;
                uint32_t off = (uint32_t)(r * 128 + seg * 16);
                uint32_t dst = sb + (c & 1) * 16384 + (off ^ ((off >> 3) & 0x70));
                cp_async16(dst, g_ebf + ((c + 2) * TCODES + r) * DIM + seg * 8);
            }
            CP_COMMIT();
        }

        // per-row (row_a, row_b) chunk max across the 128 codes
        float m0 = NEGINF, m1 = NEGINF;
#pragma unroll
        for (int t = 0; t < 16; t++) {
            m0 = fmaxf(m0, fmaxf(acc[t][0], acc[t][1]));
            m1 = fmaxf(m1, fmaxf(acc[t][2], acc[t][3]));
        }
        m0 = fmaxf(m0, __shfl_xor_sync(0xffffffffu, m0, 1));
        m0 = fmaxf(m0, __shfl_xor_sync(0xffffffffu, m0, 2));
        m1 = fmaxf(m1, __shfl_xor_sync(0xffffffffu, m1, 1));
        m1 = fmaxf(m1, __shfl_xor_sync(0xffffffffu, m1, 2));
        run0 = fmaxf(run0, m0);
        run1 = fmaxf(run1, m1);
        float thr0 = run0 - HMARGIN, thr1 = run1 - HMARGIN;

        // warp-level skip: does any lane's row have a candidate this chunk?
        bool anyc = (m0 >= thr0) || (m1 >= thr1);
        if (!__any_sync(0xffffffffu, anyc)) continue;

        // pass 1: count local candidates
        int cntl = 0;
#pragma unroll
        for (int t = 0; t < 16; t++) {
            cntl += (acc[t][0] >= thr0);
            cntl += (acc[t][1] >= thr0);
            cntl += (acc[t][2] >= thr1);
            cntl += (acc[t][3] >= thr1);
        }
        // warp inclusive prefix scan
        int pre = cntl;
#pragma unroll
        for (int o = 1; o < 32; o <<= 1) {
            int v = __shfl_up_sync(0xffffffffu, pre, o);
            if (lane >= o) pre += v;
        }
        int total = __shfl_sync(0xffffffffu, pre, 31);
        int base = 0;
        if (lane == 31 && total) base = atomicAdd(&g_cnt, total);
        base = __shfl_sync(0xffffffffu, base, 31);
        int pos = base + pre - cntl;

        if (cntl) {
            int j0 = c * TCODES + q * 2;
#pragma unroll
            for (int t = 0; t < 16; t++) {
                int j = j0 + t * 8;
                if (acc[t][0] >= thr0) { if (pos < CAP) g_cand[pos] = ((unsigned)row_a << 13) | (unsigned)j; pos++; }
                if (acc[t][1] >= thr0) { if (pos < CAP) g_cand[pos] = ((unsigned)row_a << 13) | (unsigned)(j + 1); pos++; }
                if (acc[t][2] >= thr1) { if (pos < CAP) g_cand[pos] = ((unsigned)row_b << 13) | (unsigned)j; pos++; }
                if (acc[t][3] >= thr1) { if (pos < CAP) g_cand[pos] = ((unsigned)row_b << 13) | (unsigned)(j + 1); pos++; }
            }
        }
    }
}

// ---------------------------------------------------------------------------
// Exact recheck: reference-matching fp32 d via float4 loads (ascending chain)
// ---------------------------------------------------------------------------
__global__ void vq_exact(const float* __restrict__ emb) {
    int cnt = g_cnt;
    if (cnt > CAP) cnt = CAP;
    for (int i = blockIdx.x * blockDim.x + threadIdx.x; i < cnt; i += gridDim.x * blockDim.x) {
        unsigned u = g_cand[i];
        int n = u >> 13;
        int j = u & 8191;
        const float4* zr = (const float4*)(g_zT + n * DIM);
        const float4* er = (const float4*)(emb + j * DIM);
        float dot = 0.f;
#pragma unroll
        for (int cc = 0; cc < 16; cc++) {
            float4 av = zr[cc];
            float4 bv = er[cc];
            dot = __fmaf_rn(av.x, bv.x, dot);
            dot = __fmaf_rn(av.y, bv.y, dot);
            dot = __fmaf_rn(av.z, bv.z, dot);
            dot = __fmaf_rn(av.w, bv.w, dot);
        }
        float d = __fsub_rn(__fadd_rn(g_A[n], g_B[j]), __fmul_rn(2.0f, dot));
        unsigned long long key = ((unsigned long long)__float_as_uint(d) << 13) | (unsigned)j;
        atomicMin(&g_key[n], key);
    }
}

__global__ void vq_finalize(float* __restrict__ outF) {
    int t = blockIdx.x * blockDim.x + threadIdx.x;
    if (t < N_ROWS) {
        int j = (int)(g_key[t] & 8191ull);
        g_idx[t] = j;
        outF[1 + NELEM + t] = (float)j;
    }
}

__global__ void vq_out(const float* __restrict__ z, const float* __restrict__ emb,
                       float* __restrict__ outF) {
    int t = blockIdx.x * 1024 + threadIdx.x;
    int c = (t >> 12) & 63;
    int n = ((t >> 18) << 12) | (t & 4095);
    int idx = g_idx[n];
    float zv = z[t];
    float e = emb[idx * 64 + c];
    float d1 = __fsub_rn(e, zv);
    outF[1 + t] = __fadd_rn(zv, d1);
    double s = (double)__fmul_rn(d1, d1);
#pragma unroll
    for (int o = 16; o; o >>= 1) s += __shfl_down_sync(0xffffffffu, s, o);
    __shared__ double ws[32];
    int lane = threadIdx.x & 31, w = threadIdx.x >> 5;
    if (lane == 0) ws[w] = s;
    __syncthreads();
    if (w == 0) {
        double v = ws[lane];
#pragma unroll
        for (int o = 16; o; o >>= 1) v += __shfl_down_sync(0xffffffffu, v, o);
        if (lane == 0) g_partial[blockIdx.x] = v;
    }
}

__global__ void vq_loss(float* __restrict__ outF) {
    __shared__ double sh[256];
    double s = 0.0;
    for (int i = threadIdx.x; i < 2048; i += 256) s += g_partial[i];
    sh[threadIdx.x] = s;
    __syncthreads();
    for (int st = 128; st; st >>= 1) {
        if (threadIdx.x < st) sh[threadIdx.x] += sh[threadIdx.x + st];
        __syncthreads();
    }
    if (threadIdx.x == 0) {
        float m = (float)(sh[0] / (double)NELEM);
        outF[0] = __fadd_rn(m, __fmul_rn(0.25f, m));
    }
}

extern "C" void kernel_launch(void* const* d_in, const int* in_sizes, int n_in,
                              void* d_out, int out_size) {
    const float* z = (const float*)d_in[0];
    const float* emb = (const float*)d_in[1];
    float* out = (float*)d_out;

    cudaFuncSetAttribute(vq_mma, cudaFuncAttributeMaxDynamicSharedMemorySize, SMEM_MMA);

    vq_transpose<<<512, 256>>>(z);
    vq_prep<<<2048, 256>>>(emb);
    vq_mma<<<N_ROWS / 128, 256, SMEM_MMA>>>();
    vq_exact<<<2048, 256>>>(emb);
    vq_finalize<<<32, 1024>>>(out);
    vq_out<<<2048, 1024>>>(z, emb, out);
    vq_loss<<<1, 256>>>(out);
}